// round 3
// baseline (speedup 1.0000x reference)
#include <cuda_runtime.h>

#define NN 100000
#define NE 3200000

// ---- scratch (static __device__, per allocation rules) ----
__device__ float  g_dinv[NN];        // degree -> dinv (in place)
__device__ float4 g_y[NN * 4];       // (x@W1) * dinv[row]  [N,16]
__device__ float4 g_h[NN * 4];       // conv1 accumulator -> h (in place)
__device__ float2 g_z[NN];           // (h@W2) * dinv[row]  [N,2]
__device__ float2 g_ox[NN];          // conv2 accumulator
__device__ int    g_row[NE];
__device__ int    g_col[NE];
__device__ int    g_is64;            // edge_index stored as int64?

__device__ __forceinline__ float4 f4_fma(float4 acc, float s, float4 w) {
    acc.x = fmaf(s, w.x, acc.x);
    acc.y = fmaf(s, w.y, acc.y);
    acc.z = fmaf(s, w.z, acc.z);
    acc.w = fmaf(s, w.w, acc.w);
    return acc;
}

// 0) detect int64 vs int32 edge_index layout.
// If int64 little-endian with values < 2^31, every odd int32 word is 0.
// Random indices in [0,100000) are ~never 0 sixteen times in a row.
__global__ void k_detect(const int* __restrict__ ei32) {
    int all0 = 1;
#pragma unroll
    for (int k = 1; k <= 31; k += 2) all0 &= (ei32[k] == 0);
    g_is64 = all0;
}

// 1) deg starts at 1.0 (self loop)
__global__ void k_init() {
    int i = blockIdx.x * blockDim.x + threadIdx.x;
    if (i < NN) g_dinv[i] = 1.0f;
}

// 2) decode edge index -> int32 cache + in-degree by col
__global__ void k_deg(const int* __restrict__ ei32) {
    int e = blockIdx.x * blockDim.x + threadIdx.x;
    if (e >= NE) return;
    int r, c;
    if (g_is64) {
        r = ei32[2 * e];
        c = ei32[2 * (NE + e)];
    } else {
        r = ei32[e];
        c = ei32[NE + e];
    }
    g_row[e] = r;
    g_col[e] = c;
    atomicAdd(&g_dinv[c], 1.0f);
}

// 3) dinv = rsqrt(deg); y = (x@W1)*dinv; h_acc init = self-loop contribution
__global__ void k_nodeA(const float* __restrict__ x, const float* __restrict__ W1) {
    int i = blockIdx.x * blockDim.x + threadIdx.x;
    if (i >= NN) return;
    float d = rsqrtf(g_dinv[i]);
    g_dinv[i] = d;
    float2 xv = ((const float2*)x)[i];
#pragma unroll
    for (int q = 0; q < 4; q++) {
        float4 w0 = ((const float4*)W1)[q];       // W1 row 0, cols 4q..4q+3
        float4 w1 = ((const float4*)W1)[4 + q];   // W1 row 1
        float4 xw;
        xw.x = fmaf(xv.x, w0.x, xv.y * w1.x);
        xw.y = fmaf(xv.x, w0.y, xv.y * w1.y);
        xw.z = fmaf(xv.x, w0.z, xv.y * w1.z);
        xw.w = fmaf(xv.x, w0.w, xv.y * w1.w);
        float4 yv = make_float4(xw.x * d, xw.y * d, xw.z * d, xw.w * d);
        g_y[i * 4 + q] = yv;
        g_h[i * 4 + q] = make_float4(yv.x * d, yv.y * d, yv.z * d, yv.w * d);
    }
}

// 4) conv1 scatter: h_acc[col] += y[row] * dinv[col]   (scalar REDG)
__global__ void k_scat1() {
    int e = blockIdx.x * blockDim.x + threadIdx.x;
    if (e >= NE) return;
    int r = g_row[e];
    int c = g_col[e];
    float nrm = g_dinv[c];
    float* dst = (float*)&g_h[c * 4];
#pragma unroll
    for (int q = 0; q < 4; q++) {
        float4 v = g_y[r * 4 + q];
        atomicAdd(dst + q * 4 + 0, v.x * nrm);
        atomicAdd(dst + q * 4 + 1, v.y * nrm);
        atomicAdd(dst + q * 4 + 2, v.z * nrm);
        atomicAdd(dst + q * 4 + 3, v.w * nrm);
    }
}

// 5) h = h_acc + b1 (in place); z = (h@W2)*dinv; ox init = self-loop contribution
__global__ void k_nodeB(const float* __restrict__ b1, const float* __restrict__ W2) {
    int i = blockIdx.x * blockDim.x + threadIdx.x;
    if (i >= NN) return;
    float z0 = 0.f, z1 = 0.f;
#pragma unroll
    for (int q = 0; q < 4; q++) {
        float4 bq = ((const float4*)b1)[q];
        float4 h = g_h[i * 4 + q];
        h.x += bq.x; h.y += bq.y; h.z += bq.z; h.w += bq.w;
        g_h[i * 4 + q] = h;
        // W2 is [16,2] row-major
        float2 wa = ((const float2*)W2)[q * 4 + 0];
        float2 wb = ((const float2*)W2)[q * 4 + 1];
        float2 wc = ((const float2*)W2)[q * 4 + 2];
        float2 wd = ((const float2*)W2)[q * 4 + 3];
        z0 = fmaf(h.x, wa.x, z0); z1 = fmaf(h.x, wa.y, z1);
        z0 = fmaf(h.y, wb.x, z0); z1 = fmaf(h.y, wb.y, z1);
        z0 = fmaf(h.z, wc.x, z0); z1 = fmaf(h.z, wc.y, z1);
        z0 = fmaf(h.w, wd.x, z0); z1 = fmaf(h.w, wd.y, z1);
    }
    float d = g_dinv[i];
    g_z[i] = make_float2(z0 * d, z1 * d);
    g_ox[i] = make_float2(z0 * d * d, z1 * d * d);
}

// 6) fused edge pass: MLP(concat(h[r], ea, h[c]))@We+be -> relu -> log_softmax(4)
//    + conv2 scatter (ox[col] += z[row]*dinv[col])
__global__ void k_edge(const float* __restrict__ ea,
                       const float* __restrict__ We,
                       const float* __restrict__ be,
                       float* __restrict__ out_e) {
    __shared__ float4 sW[34];  // 33 rows of We (each row = 4 floats) + be
    int tid = threadIdx.x;
    if (tid < 33) sW[tid] = ((const float4*)We)[tid];
    if (tid == 33) sW[33] = *((const float4*)be);
    __syncthreads();

    int e = blockIdx.x * blockDim.x + tid;
    if (e >= NE) return;
    int r = g_row[e];
    int c = g_col[e];

    float4 acc = sW[33];                 // be
    float eav = ea[e];
    acc = f4_fma(acc, eav, sW[16]);      // edge_attr * We row 16

#pragma unroll
    for (int q = 0; q < 4; q++) {
        float4 hr = g_h[r * 4 + q];      // e_in[0:16] = h[row]
        acc = f4_fma(acc, hr.x, sW[q * 4 + 0]);
        acc = f4_fma(acc, hr.y, sW[q * 4 + 1]);
        acc = f4_fma(acc, hr.z, sW[q * 4 + 2]);
        acc = f4_fma(acc, hr.w, sW[q * 4 + 3]);
    }
#pragma unroll
    for (int q = 0; q < 4; q++) {
        float4 hc = g_h[c * 4 + q];      // e_in[17:33] = h[col]
        acc = f4_fma(acc, hc.x, sW[17 + q * 4 + 0]);
        acc = f4_fma(acc, hc.y, sW[17 + q * 4 + 1]);
        acc = f4_fma(acc, hc.z, sW[17 + q * 4 + 2]);
        acc = f4_fma(acc, hc.w, sW[17 + q * 4 + 3]);
    }
    // relu
    acc.x = fmaxf(acc.x, 0.f); acc.y = fmaxf(acc.y, 0.f);
    acc.z = fmaxf(acc.z, 0.f); acc.w = fmaxf(acc.w, 0.f);
    // log_softmax over 4
    float m = fmaxf(fmaxf(acc.x, acc.y), fmaxf(acc.z, acc.w));
    float s = __expf(acc.x - m) + __expf(acc.y - m) + __expf(acc.z - m) + __expf(acc.w - m);
    float l = m + __logf(s);
    ((float4*)out_e)[e] = make_float4(acc.x - l, acc.y - l, acc.z - l, acc.w - l);

    // conv2 scatter (scalar REDG)
    float nrm = g_dinv[c];
    float2 zr = g_z[r];
    atomicAdd(&g_ox[c].x, zr.x * nrm);
    atomicAdd(&g_ox[c].y, zr.y * nrm);
}

// 7) node output: log_softmax(ox + b2) over 2 classes
__global__ void k_nodeC(const float* __restrict__ b2, float* __restrict__ out_n) {
    int i = blockIdx.x * blockDim.x + threadIdx.x;
    if (i >= NN) return;
    float2 bb = *((const float2*)b2);
    float2 v = g_ox[i];
    v.x += bb.x; v.y += bb.y;
    float m = fmaxf(v.x, v.y);
    float l = m + __logf(__expf(v.x - m) + __expf(v.y - m));
    ((float2*)out_n)[i] = make_float2(v.x - l, v.y - l);
}

extern "C" void kernel_launch(void* const* d_in, const int* in_sizes, int n_in,
                              void* d_out, int out_size) {
    // Identify inputs by element count (robust to metadata ordering & dtype):
    //   x=200000, edge_index=6400000 (int64) or 12800000 (int32 view),
    //   edge_attr=3200000, W1/W2=32 (first seen = W1), b1=16, We=132, be=4, b2=2
    const float *x = 0, *ea = 0, *W1 = 0, *b1 = 0, *We = 0, *be = 0, *W2 = 0, *b2 = 0;
    const int* ei32 = 0;
    for (int i = 0; i < n_in; i++) {
        switch (in_sizes[i]) {
            case 200000:   x    = (const float*)d_in[i]; break;
            case 6400000:  ei32 = (const int*)d_in[i];   break;
            case 12800000: ei32 = (const int*)d_in[i];   break;
            case 3200000:  ea   = (const float*)d_in[i]; break;
            case 132:      We   = (const float*)d_in[i]; break;
            case 16:       b1   = (const float*)d_in[i]; break;
            case 4:        be   = (const float*)d_in[i]; break;
            case 2:        b2   = (const float*)d_in[i]; break;
            case 32:
                if (!W1) W1 = (const float*)d_in[i];
                else     W2 = (const float*)d_in[i];
                break;
            default: break;
        }
    }

    float* out = (float*)d_out;
    float* out_n = out;             // [N,2]
    float* out_e = out + 2 * NN;    // [E,4]

    const int BT = 256;
    const int NB_N = (NN + BT - 1) / BT;
    const int NB_E = (NE + BT - 1) / BT;

    k_detect<<<1, 1>>>(ei32);
    k_init  <<<NB_N, BT>>>();
    k_deg   <<<NB_E, BT>>>(ei32);
    k_nodeA <<<NB_N, BT>>>(x, W1);
    k_scat1 <<<NB_E, BT>>>();
    k_nodeB <<<NB_N, BT>>>(b1, W2);
    k_edge  <<<NB_E, BT>>>(ea, We, be, out_e);
    k_nodeC <<<NB_N, BT>>>(b2, out_n);
}

// round 4
// speedup vs baseline: 1.7568x; 1.7568x over previous
#include <cuda_runtime.h>

#define NN 100000
#define NE 3200000

// ---- scratch (static __device__) ----
__device__ float  g_dinv[NN];        // degree -> dinv (in place)
__device__ float4 g_y[NN * 4];       // (x@W1)*dinv[row]  [N,16]
__device__ float4 g_h[NN * 4];       // conv1 accumulator (unscaled) -> h (in place)
__device__ float2 g_z[NN];           // (h@W2)*dinv[row]  [N,2]
__device__ float2 g_ox[NN];          // conv2 accumulator (unscaled)
__device__ int2   g_edge[NE];        // (row, col) packed
__device__ int    g_is64;

// ---- vectorized L2 reductions (cvta to global space first: fixes err 717) ----
__device__ __forceinline__ void red_add_v4(float4* addr, float4 v) {
    unsigned long long ga;
    asm("cvta.to.global.u64 %0, %1;" : "=l"(ga) : "l"(addr));
    asm volatile("red.global.add.v4.f32 [%0], {%1, %2, %3, %4};"
                 :: "l"(ga), "f"(v.x), "f"(v.y), "f"(v.z), "f"(v.w) : "memory");
}
__device__ __forceinline__ void red_add_v2(float2* addr, float a, float b) {
    unsigned long long ga;
    asm("cvta.to.global.u64 %0, %1;" : "=l"(ga) : "l"(addr));
    asm volatile("red.global.add.v2.f32 [%0], {%1, %2};"
                 :: "l"(ga), "f"(a), "f"(b) : "memory");
}

__device__ __forceinline__ float4 f4_fma(float4 acc, float s, float4 w) {
    acc.x = fmaf(s, w.x, acc.x);
    acc.y = fmaf(s, w.y, acc.y);
    acc.z = fmaf(s, w.z, acc.z);
    acc.w = fmaf(s, w.w, acc.w);
    return acc;
}

// 0) detect int64 vs int32 edge_index layout (odd words all zero => int64)
__global__ void k_detect(const int* __restrict__ ei32) {
    int all0 = 1;
#pragma unroll
    for (int k = 1; k <= 31; k += 2) all0 &= (ei32[k] == 0);
    g_is64 = all0;
}

// 1) deg starts at 1.0 (self loop)
__global__ void k_init() {
    int i = blockIdx.x * blockDim.x + threadIdx.x;
    if (i < NN) g_dinv[i] = 1.0f;
}

// 2) decode edge index -> packed int2 + in-degree by col
__global__ void k_deg(const int* __restrict__ ei32) {
    int e = blockIdx.x * blockDim.x + threadIdx.x;
    if (e >= NE) return;
    int r, c;
    if (g_is64) {
        r = ei32[2 * e];
        c = ei32[2 * (NE + e)];
    } else {
        r = ei32[e];
        c = ei32[NE + e];
    }
    g_edge[e] = make_int2(r, c);
    atomicAdd(&g_dinv[c], 1.0f);
}

// 3) dinv = rsqrt(deg); y = (x@W1)*dinv; h_acc init = y (self-loop, unscaled)
__global__ void k_nodeA(const float* __restrict__ x, const float* __restrict__ W1) {
    int i = blockIdx.x * blockDim.x + threadIdx.x;
    if (i >= NN) return;
    float d = rsqrtf(g_dinv[i]);
    g_dinv[i] = d;
    float2 xv = ((const float2*)x)[i];
#pragma unroll
    for (int q = 0; q < 4; q++) {
        float4 w0 = ((const float4*)W1)[q];       // W1 row 0, cols 4q..4q+3
        float4 w1 = ((const float4*)W1)[4 + q];   // W1 row 1
        float4 yv;
        yv.x = fmaf(xv.x, w0.x, xv.y * w1.x) * d;
        yv.y = fmaf(xv.x, w0.y, xv.y * w1.y) * d;
        yv.z = fmaf(xv.x, w0.z, xv.y * w1.z) * d;
        yv.w = fmaf(xv.x, w0.w, xv.y * w1.w) * d;
        g_y[i * 4 + q] = yv;
        g_h[i * 4 + q] = yv;   // self-loop term (col scale applied later)
    }
}

// 4) conv1 scatter: h_acc[col] += y[row]   (pure gather + v4 red, no scaling)
__global__ void k_scat1() {
    int e = blockIdx.x * blockDim.x + threadIdx.x;
    if (e >= NE) return;
    int2 rc = g_edge[e];
#pragma unroll
    for (int q = 0; q < 4; q++) {
        red_add_v4(&g_h[rc.y * 4 + q], g_y[rc.x * 4 + q]);
    }
}

// 5) h = h_acc*dinv + b1 (in place); z = (h@W2)*dinv; ox init = z (self-loop)
__global__ void k_nodeB(const float* __restrict__ b1, const float* __restrict__ W2) {
    int i = blockIdx.x * blockDim.x + threadIdx.x;
    if (i >= NN) return;
    float d = g_dinv[i];
    float z0 = 0.f, z1 = 0.f;
#pragma unroll
    for (int q = 0; q < 4; q++) {
        float4 bq = ((const float4*)b1)[q];
        float4 h = g_h[i * 4 + q];
        h.x = fmaf(h.x, d, bq.x);
        h.y = fmaf(h.y, d, bq.y);
        h.z = fmaf(h.z, d, bq.z);
        h.w = fmaf(h.w, d, bq.w);
        g_h[i * 4 + q] = h;
        // W2 is [16,2] row-major
        float2 wa = ((const float2*)W2)[q * 4 + 0];
        float2 wb = ((const float2*)W2)[q * 4 + 1];
        float2 wc = ((const float2*)W2)[q * 4 + 2];
        float2 wd = ((const float2*)W2)[q * 4 + 3];
        z0 = fmaf(h.x, wa.x, z0); z1 = fmaf(h.x, wa.y, z1);
        z0 = fmaf(h.y, wb.x, z0); z1 = fmaf(h.y, wb.y, z1);
        z0 = fmaf(h.z, wc.x, z0); z1 = fmaf(h.z, wc.y, z1);
        z0 = fmaf(h.w, wd.x, z0); z1 = fmaf(h.w, wd.y, z1);
    }
    g_z[i] = make_float2(z0 * d, z1 * d);
    g_ox[i] = make_float2(z0 * d, z1 * d);   // self-loop term (col scale later)
}

// 6) fused edge pass: MLP(concat(h[r], ea, h[c]))@We+be -> relu -> log_softmax(4)
//    + conv2 scatter (ox_acc[col] += z[row], unscaled)
__global__ void k_edge(const float* __restrict__ ea,
                       const float* __restrict__ We,
                       const float* __restrict__ be,
                       float* __restrict__ out_e) {
    __shared__ float4 sW[34];  // 33 rows of We + be
    int tid = threadIdx.x;
    if (tid < 33) sW[tid] = ((const float4*)We)[tid];
    if (tid == 33) sW[33] = *((const float4*)be);
    __syncthreads();

    int e = blockIdx.x * blockDim.x + tid;
    if (e >= NE) return;
    int2 rc = g_edge[e];
    int r = rc.x, c = rc.y;

    float4 acc = sW[33];                 // be
    acc = f4_fma(acc, ea[e], sW[16]);    // edge_attr * We row 16

#pragma unroll
    for (int q = 0; q < 4; q++) {
        float4 hr = g_h[r * 4 + q];      // e_in[0:16] = h[row]
        acc = f4_fma(acc, hr.x, sW[q * 4 + 0]);
        acc = f4_fma(acc, hr.y, sW[q * 4 + 1]);
        acc = f4_fma(acc, hr.z, sW[q * 4 + 2]);
        acc = f4_fma(acc, hr.w, sW[q * 4 + 3]);
    }
#pragma unroll
    for (int q = 0; q < 4; q++) {
        float4 hc = g_h[c * 4 + q];      // e_in[17:33] = h[col]
        acc = f4_fma(acc, hc.x, sW[17 + q * 4 + 0]);
        acc = f4_fma(acc, hc.y, sW[17 + q * 4 + 1]);
        acc = f4_fma(acc, hc.z, sW[17 + q * 4 + 2]);
        acc = f4_fma(acc, hc.w, sW[17 + q * 4 + 3]);
    }
    acc.x = fmaxf(acc.x, 0.f); acc.y = fmaxf(acc.y, 0.f);
    acc.z = fmaxf(acc.z, 0.f); acc.w = fmaxf(acc.w, 0.f);
    float m = fmaxf(fmaxf(acc.x, acc.y), fmaxf(acc.z, acc.w));
    float s = __expf(acc.x - m) + __expf(acc.y - m) + __expf(acc.z - m) + __expf(acc.w - m);
    float l = m + __logf(s);
    ((float4*)out_e)[e] = make_float4(acc.x - l, acc.y - l, acc.z - l, acc.w - l);

    // conv2 scatter (unscaled, v2 red)
    float2 zr = g_z[r];
    red_add_v2(&g_ox[c], zr.x, zr.y);
}

// 7) node output: log_softmax(ox_acc*dinv + b2) over 2 classes
__global__ void k_nodeC(const float* __restrict__ b2, float* __restrict__ out_n) {
    int i = blockIdx.x * blockDim.x + threadIdx.x;
    if (i >= NN) return;
    float d = g_dinv[i];
    float2 bb = *((const float2*)b2);
    float2 v = g_ox[i];
    v.x = fmaf(v.x, d, bb.x);
    v.y = fmaf(v.y, d, bb.y);
    float m = fmaxf(v.x, v.y);
    float l = m + __logf(__expf(v.x - m) + __expf(v.y - m));
    ((float2*)out_n)[i] = make_float2(v.x - l, v.y - l);
}

extern "C" void kernel_launch(void* const* d_in, const int* in_sizes, int n_in,
                              void* d_out, int out_size) {
    // Identify inputs by element count (robust to ordering & dtype):
    const float *x = 0, *ea = 0, *W1 = 0, *b1 = 0, *We = 0, *be = 0, *W2 = 0, *b2 = 0;
    const int* ei32 = 0;
    for (int i = 0; i < n_in; i++) {
        switch (in_sizes[i]) {
            case 200000:   x    = (const float*)d_in[i]; break;
            case 6400000:  ei32 = (const int*)d_in[i];   break;
            case 12800000: ei32 = (const int*)d_in[i];   break;
            case 3200000:  ea   = (const float*)d_in[i]; break;
            case 132:      We   = (const float*)d_in[i]; break;
            case 16:       b1   = (const float*)d_in[i]; break;
            case 4:        be   = (const float*)d_in[i]; break;
            case 2:        b2   = (const float*)d_in[i]; break;
            case 32:
                if (!W1) W1 = (const float*)d_in[i];
                else     W2 = (const float*)d_in[i];
                break;
            default: break;
        }
    }

    float* out = (float*)d_out;
    float* out_n = out;             // [N,2]
    float* out_e = out + 2 * NN;    // [E,4]

    const int BT = 256;
    const int NB_N = (NN + BT - 1) / BT;
    const int NB_E = (NE + BT - 1) / BT;

    k_detect<<<1, 1>>>(ei32);
    k_init  <<<NB_N, BT>>>();
    k_deg   <<<NB_E, BT>>>(ei32);
    k_nodeA <<<NB_N, BT>>>(x, W1);
    k_scat1 <<<NB_E, BT>>>();
    k_nodeB <<<NB_N, BT>>>(b1, W2);
    k_edge  <<<NB_E, BT>>>(ea, We, be, out_e);
    k_nodeC <<<NB_N, BT>>>(b2, out_n);
}

// round 5
// speedup vs baseline: 2.3458x; 1.3353x over previous
#include <cuda_runtime.h>

#define NN 100000
#define NE 3200000

// ---- scratch (static __device__) ----
__device__ float  g_dinv[NN];        // degree -> dinv (in place)
__device__ float4 g_y[NN * 4];       // (x@W1)*dinv[row]  [N,16]
__device__ float4 g_h[NN * 4];       // conv1 accumulator (unscaled) -> h (in place)
__device__ float4 g_ra[NN * 2];      // per-node r-side pack: [2i]=pr (We[0:16]^T h), [2i+1]=(z.x,z.y,-,-)
__device__ float4 g_pc[NN];          // per-node c-side proj: We[17:33]^T h
__device__ float2 g_ox[NN];          // conv2 accumulator (unscaled)
__device__ int2   g_edge[NE];        // (row, col) packed
__device__ int    g_is64;

// ---- vectorized L2 reductions (global address space) ----
__device__ __forceinline__ void red_add_v4(float4* addr, float4 v) {
    unsigned long long ga;
    asm("cvta.to.global.u64 %0, %1;" : "=l"(ga) : "l"(addr));
    asm volatile("red.global.add.v4.f32 [%0], {%1, %2, %3, %4};"
                 :: "l"(ga), "f"(v.x), "f"(v.y), "f"(v.z), "f"(v.w) : "memory");
}
__device__ __forceinline__ void red_add_v2(float2* addr, float a, float b) {
    unsigned long long ga;
    asm("cvta.to.global.u64 %0, %1;" : "=l"(ga) : "l"(addr));
    asm volatile("red.global.add.v2.f32 [%0], {%1, %2};"
                 :: "l"(ga), "f"(a), "f"(b) : "memory");
}

// 0) detect int64 vs int32 edge_index layout (odd words all zero => int64)
__global__ void k_detect(const int* __restrict__ ei32) {
    int all0 = 1;
#pragma unroll
    for (int k = 1; k <= 31; k += 2) all0 &= (ei32[k] == 0);
    g_is64 = all0;
}

// 1) deg starts at 1.0 (self loop)
__global__ void k_init() {
    int i = blockIdx.x * blockDim.x + threadIdx.x;
    if (i < NN) g_dinv[i] = 1.0f;
}

// 2) decode edge index -> packed int2 + in-degree by col
__global__ void k_deg(const int* __restrict__ ei32) {
    int e = blockIdx.x * blockDim.x + threadIdx.x;
    if (e >= NE) return;
    int r, c;
    if (g_is64) {
        r = ei32[2 * e];
        c = ei32[2 * (NE + e)];
    } else {
        r = ei32[e];
        c = ei32[NE + e];
    }
    g_edge[e] = make_int2(r, c);
    atomicAdd(&g_dinv[c], 1.0f);
}

// 3) dinv = rsqrt(deg); y = (x@W1)*dinv; h_acc init = y (self-loop, unscaled)
__global__ void k_nodeA(const float* __restrict__ x, const float* __restrict__ W1) {
    int i = blockIdx.x * blockDim.x + threadIdx.x;
    if (i >= NN) return;
    float d = rsqrtf(g_dinv[i]);
    g_dinv[i] = d;
    float2 xv = ((const float2*)x)[i];
#pragma unroll
    for (int q = 0; q < 4; q++) {
        float4 w0 = ((const float4*)W1)[q];       // W1 row 0, cols 4q..4q+3
        float4 w1 = ((const float4*)W1)[4 + q];   // W1 row 1
        float4 yv;
        yv.x = fmaf(xv.x, w0.x, xv.y * w1.x) * d;
        yv.y = fmaf(xv.x, w0.y, xv.y * w1.y) * d;
        yv.z = fmaf(xv.x, w0.z, xv.y * w1.z) * d;
        yv.w = fmaf(xv.x, w0.w, xv.y * w1.w) * d;
        g_y[i * 4 + q] = yv;
        g_h[i * 4 + q] = yv;   // self-loop term (col scale applied later)
    }
}

// 4) conv1 scatter: h_acc[col] += y[row]   (pure gather + v4 red)
__global__ void k_scat1() {
    int e = blockIdx.x * blockDim.x + threadIdx.x;
    if (e >= NE) return;
    int2 rc = g_edge[e];
#pragma unroll
    for (int q = 0; q < 4; q++) {
        red_add_v4(&g_h[rc.y * 4 + q], g_y[rc.x * 4 + q]);
    }
}

// 5) h = h_acc*dinv + b1; precompute per-node: pr = We[0:16]^T h, pc = We[17:33]^T h,
//    z = (h@W2)*dinv; ox init = z (self-loop, col scale later)
__global__ void k_nodeB(const float* __restrict__ b1, const float* __restrict__ W2,
                        const float* __restrict__ We) {
    int i = blockIdx.x * blockDim.x + threadIdx.x;
    if (i >= NN) return;
    float d = g_dinv[i];
    float z0 = 0.f, z1 = 0.f;
    float4 pr = make_float4(0.f, 0.f, 0.f, 0.f);
    float4 pc = make_float4(0.f, 0.f, 0.f, 0.f);
#pragma unroll
    for (int q = 0; q < 4; q++) {
        float4 bq = ((const float4*)b1)[q];
        float4 h = g_h[i * 4 + q];
        h.x = fmaf(h.x, d, bq.x);
        h.y = fmaf(h.y, d, bq.y);
        h.z = fmaf(h.z, d, bq.z);
        h.w = fmaf(h.w, d, bq.w);
        g_h[i * 4 + q] = h;
        float hv[4] = {h.x, h.y, h.z, h.w};
#pragma unroll
        for (int j = 0; j < 4; j++) {
            int k = q * 4 + j;
            float s = hv[j];
            // W2 [16,2] row-major
            float2 w2 = ((const float2*)W2)[k];
            z0 = fmaf(s, w2.x, z0);
            z1 = fmaf(s, w2.y, z1);
            // We rows k (r-side) and 17+k (c-side), each 4 floats
            float4 wr = ((const float4*)We)[k];
            float4 wc = ((const float4*)We)[17 + k];
            pr.x = fmaf(s, wr.x, pr.x); pr.y = fmaf(s, wr.y, pr.y);
            pr.z = fmaf(s, wr.z, pr.z); pr.w = fmaf(s, wr.w, pr.w);
            pc.x = fmaf(s, wc.x, pc.x); pc.y = fmaf(s, wc.y, pc.y);
            pc.z = fmaf(s, wc.z, pc.z); pc.w = fmaf(s, wc.w, pc.w);
        }
    }
    g_ra[i * 2]     = pr;
    g_ra[i * 2 + 1] = make_float4(z0 * d, z1 * d, 0.f, 0.f);
    g_pc[i] = pc;
    g_ox[i] = make_float2(z0 * d, z1 * d);   // self-loop term
}

// 6) edge pass: acc = pr[r] + pc[c] + ea*We16 + be -> relu -> log_softmax(4)
//    + conv2 scatter (ox_acc[col] += z[row])
__global__ void k_edge(const float* __restrict__ ea,
                       const float* __restrict__ We,
                       const float* __restrict__ be,
                       float* __restrict__ out_e) {
    int e = blockIdx.x * blockDim.x + threadIdx.x;
    if (e >= NE) return;
    // broadcast weights (L1/const-cache hit)
    float4 w16 = __ldg((const float4*)We + 16);
    float4 bev = __ldg((const float4*)be);

    int2 rc = g_edge[e];
    int r = rc.x, c = rc.y;

    float4 pr  = g_ra[r * 2];
    float4 zr  = g_ra[r * 2 + 1];
    float4 pc  = g_pc[c];
    float  eav = ea[e];

    float4 acc;
    acc.x = fmaf(eav, w16.x, bev.x) + pr.x + pc.x;
    acc.y = fmaf(eav, w16.y, bev.y) + pr.y + pc.y;
    acc.z = fmaf(eav, w16.z, bev.z) + pr.z + pc.z;
    acc.w = fmaf(eav, w16.w, bev.w) + pr.w + pc.w;

    acc.x = fmaxf(acc.x, 0.f); acc.y = fmaxf(acc.y, 0.f);
    acc.z = fmaxf(acc.z, 0.f); acc.w = fmaxf(acc.w, 0.f);
    float m = fmaxf(fmaxf(acc.x, acc.y), fmaxf(acc.z, acc.w));
    float s = __expf(acc.x - m) + __expf(acc.y - m) + __expf(acc.z - m) + __expf(acc.w - m);
    float l = m + __logf(s);
    ((float4*)out_e)[e] = make_float4(acc.x - l, acc.y - l, acc.z - l, acc.w - l);

    // conv2 scatter (unscaled, v2 red)
    red_add_v2(&g_ox[c], zr.x, zr.y);
}

// 7) node output: log_softmax(ox_acc*dinv + b2) over 2 classes
__global__ void k_nodeC(const float* __restrict__ b2, float* __restrict__ out_n) {
    int i = blockIdx.x * blockDim.x + threadIdx.x;
    if (i >= NN) return;
    float d = g_dinv[i];
    float2 bb = *((const float2*)b2);
    float2 v = g_ox[i];
    v.x = fmaf(v.x, d, bb.x);
    v.y = fmaf(v.y, d, bb.y);
    float m = fmaxf(v.x, v.y);
    float l = m + __logf(__expf(v.x - m) + __expf(v.y - m));
    ((float2*)out_n)[i] = make_float2(v.x - l, v.y - l);
}

extern "C" void kernel_launch(void* const* d_in, const int* in_sizes, int n_in,
                              void* d_out, int out_size) {
    // Identify inputs by element count (robust to ordering & dtype):
    const float *x = 0, *ea = 0, *W1 = 0, *b1 = 0, *We = 0, *be = 0, *W2 = 0, *b2 = 0;
    const int* ei32 = 0;
    for (int i = 0; i < n_in; i++) {
        switch (in_sizes[i]) {
            case 200000:   x    = (const float*)d_in[i]; break;
            case 6400000:  ei32 = (const int*)d_in[i];   break;
            case 12800000: ei32 = (const int*)d_in[i];   break;
            case 3200000:  ea   = (const float*)d_in[i]; break;
            case 132:      We   = (const float*)d_in[i]; break;
            case 16:       b1   = (const float*)d_in[i]; break;
            case 4:        be   = (const float*)d_in[i]; break;
            case 2:        b2   = (const float*)d_in[i]; break;
            case 32:
                if (!W1) W1 = (const float*)d_in[i];
                else     W2 = (const float*)d_in[i];
                break;
            default: break;
        }
    }

    float* out = (float*)d_out;
    float* out_n = out;             // [N,2]
    float* out_e = out + 2 * NN;    // [E,4]

    const int BT = 256;
    const int NB_N = (NN + BT - 1) / BT;
    const int NB_E = (NE + BT - 1) / BT;

    k_detect<<<1, 1>>>(ei32);
    k_init  <<<NB_N, BT>>>();
    k_deg   <<<NB_E, BT>>>(ei32);
    k_nodeA <<<NB_N, BT>>>(x, W1);
    k_scat1 <<<NB_E, BT>>>();
    k_nodeB <<<NB_N, BT>>>(b1, W2, We);
    k_edge  <<<NB_E, BT>>>(ea, We, be, out_e);
    k_nodeC <<<NB_N, BT>>>(b2, out_n);
}

// round 6
// speedup vs baseline: 3.8637x; 1.6470x over previous
#include <cuda_runtime.h>

#define NN 100000
#define NE 3200000

// ---- scratch (static __device__) ----
__device__ float  g_dinv[NN];        // degree -> dinv (in place)
__device__ float2 g_s[NN];           // s[i] = dinv[i] * x[i]  (rank-2 coords of y[i])
__device__ float2 g_ab[NN];          // conv1 accumulator in rank-2 basis (init = s[i])
__device__ float4 g_ra[NN * 2];      // r-side pack: [2i]=pr (We[0:16]^T h), [2i+1]=(z.x,z.y,-,-)
__device__ float4 g_pc[NN];          // c-side proj: We[17:33]^T h
__device__ float2 g_ox[NN];          // conv2 accumulator (unscaled)
__device__ int2   g_edge[NE];        // (row, col) packed
__device__ int    g_is64;

// ---- vectorized L2 reduction (global address space) ----
__device__ __forceinline__ void red_add_v2(float2* addr, float a, float b) {
    unsigned long long ga;
    asm("cvta.to.global.u64 %0, %1;" : "=l"(ga) : "l"(addr));
    asm volatile("red.global.add.v2.f32 [%0], {%1, %2};"
                 :: "l"(ga), "f"(a), "f"(b) : "memory");
}

// 0) detect int64 vs int32 edge_index layout (odd words all zero => int64)
__global__ void k_detect(const int* __restrict__ ei32) {
    int all0 = 1;
#pragma unroll
    for (int k = 1; k <= 31; k += 2) all0 &= (ei32[k] == 0);
    g_is64 = all0;
}

// 1) deg starts at 1.0 (self loop)
__global__ void k_init() {
    int i = blockIdx.x * blockDim.x + threadIdx.x;
    if (i < NN) g_dinv[i] = 1.0f;
}

// 2) decode edge index -> packed int2 + in-degree by col
__global__ void k_deg(const int* __restrict__ ei32) {
    int e = blockIdx.x * blockDim.x + threadIdx.x;
    if (e >= NE) return;
    int r, c;
    if (g_is64) {
        r = ei32[2 * e];
        c = ei32[2 * (NE + e)];
    } else {
        r = ei32[e];
        c = ei32[NE + e];
    }
    g_edge[e] = make_int2(r, c);
    atomicAdd(&g_dinv[c], 1.0f);
}

// 3) dinv = rsqrt(deg); s = dinv*x; ab init = s (self-loop)
__global__ void k_nodeA(const float* __restrict__ x) {
    int i = blockIdx.x * blockDim.x + threadIdx.x;
    if (i >= NN) return;
    float d = rsqrtf(g_dinv[i]);
    g_dinv[i] = d;
    float2 xv = ((const float2*)x)[i];
    float2 s = make_float2(xv.x * d, xv.y * d);
    g_s[i]  = s;
    g_ab[i] = s;
}

// 4) conv1 scatter in rank-2 basis: ab[col] += s[row]   (one v2 red per edge)
__global__ void k_scat1() {
    int e = blockIdx.x * blockDim.x + threadIdx.x;
    if (e >= NE) return;
    int2 rc = g_edge[e];
    float2 s = g_s[rc.x];
    red_add_v2(&g_ab[rc.y], s.x, s.y);
}

// 5) expand to 16 dims: h = dinv*(ab.x*W1row0 + ab.y*W1row1) + b1;
//    precompute pr = We[0:16]^T h, pc = We[17:33]^T h, z = (h@W2)*dinv;
//    ox init = z (self-loop, col scale later)
__global__ void k_nodeB(const float* __restrict__ W1, const float* __restrict__ b1,
                        const float* __restrict__ W2, const float* __restrict__ We) {
    int i = blockIdx.x * blockDim.x + threadIdx.x;
    if (i >= NN) return;
    float d = g_dinv[i];
    float2 ab = g_ab[i];
    float ax = ab.x * d, bx = ab.y * d;
    float z0 = 0.f, z1 = 0.f;
    float4 pr = make_float4(0.f, 0.f, 0.f, 0.f);
    float4 pc = make_float4(0.f, 0.f, 0.f, 0.f);
#pragma unroll
    for (int q = 0; q < 4; q++) {
        float4 w0 = ((const float4*)W1)[q];       // W1 row 0, cols 4q..4q+3
        float4 w1 = ((const float4*)W1)[4 + q];   // W1 row 1
        float4 bq = ((const float4*)b1)[q];
        float4 h;
        h.x = fmaf(ax, w0.x, fmaf(bx, w1.x, bq.x));
        h.y = fmaf(ax, w0.y, fmaf(bx, w1.y, bq.y));
        h.z = fmaf(ax, w0.z, fmaf(bx, w1.z, bq.z));
        h.w = fmaf(ax, w0.w, fmaf(bx, w1.w, bq.w));
        float hv[4] = {h.x, h.y, h.z, h.w};
#pragma unroll
        for (int j = 0; j < 4; j++) {
            int k = q * 4 + j;
            float s = hv[j];
            float2 w2 = ((const float2*)W2)[k];        // W2 [16,2] row-major
            z0 = fmaf(s, w2.x, z0);
            z1 = fmaf(s, w2.y, z1);
            float4 wr = ((const float4*)We)[k];        // We row k (r-side)
            float4 wc = ((const float4*)We)[17 + k];   // We row 17+k (c-side)
            pr.x = fmaf(s, wr.x, pr.x); pr.y = fmaf(s, wr.y, pr.y);
            pr.z = fmaf(s, wr.z, pr.z); pr.w = fmaf(s, wr.w, pr.w);
            pc.x = fmaf(s, wc.x, pc.x); pc.y = fmaf(s, wc.y, pc.y);
            pc.z = fmaf(s, wc.z, pc.z); pc.w = fmaf(s, wc.w, pc.w);
        }
    }
    g_ra[i * 2]     = pr;
    g_ra[i * 2 + 1] = make_float4(z0 * d, z1 * d, 0.f, 0.f);
    g_pc[i] = pc;
    g_ox[i] = make_float2(z0 * d, z1 * d);   // self-loop term
}

// 6) edge pass: acc = pr[r] + pc[c] + ea*We16 + be -> relu -> log_softmax(4)
//    + conv2 scatter (ox_acc[col] += z[row])
__global__ void k_edge(const float* __restrict__ ea,
                       const float* __restrict__ We,
                       const float* __restrict__ be,
                       float* __restrict__ out_e) {
    int e = blockIdx.x * blockDim.x + threadIdx.x;
    if (e >= NE) return;
    float4 w16 = __ldg((const float4*)We + 16);
    float4 bev = __ldg((const float4*)be);

    int2 rc = g_edge[e];
    int r = rc.x, c = rc.y;

    float4 pr  = g_ra[r * 2];
    float4 zr  = g_ra[r * 2 + 1];
    float4 pc  = g_pc[c];
    float  eav = ea[e];

    float4 acc;
    acc.x = fmaf(eav, w16.x, bev.x) + pr.x + pc.x;
    acc.y = fmaf(eav, w16.y, bev.y) + pr.y + pc.y;
    acc.z = fmaf(eav, w16.z, bev.z) + pr.z + pc.z;
    acc.w = fmaf(eav, w16.w, bev.w) + pr.w + pc.w;

    acc.x = fmaxf(acc.x, 0.f); acc.y = fmaxf(acc.y, 0.f);
    acc.z = fmaxf(acc.z, 0.f); acc.w = fmaxf(acc.w, 0.f);
    float m = fmaxf(fmaxf(acc.x, acc.y), fmaxf(acc.z, acc.w));
    float s = __expf(acc.x - m) + __expf(acc.y - m) + __expf(acc.z - m) + __expf(acc.w - m);
    float l = m + __logf(s);
    ((float4*)out_e)[e] = make_float4(acc.x - l, acc.y - l, acc.z - l, acc.w - l);

    // conv2 scatter (unscaled, v2 red)
    red_add_v2(&g_ox[c], zr.x, zr.y);
}

// 7) node output: log_softmax(ox_acc*dinv + b2) over 2 classes
__global__ void k_nodeC(const float* __restrict__ b2, float* __restrict__ out_n) {
    int i = blockIdx.x * blockDim.x + threadIdx.x;
    if (i >= NN) return;
    float d = g_dinv[i];
    float2 bb = *((const float2*)b2);
    float2 v = g_ox[i];
    v.x = fmaf(v.x, d, bb.x);
    v.y = fmaf(v.y, d, bb.y);
    float m = fmaxf(v.x, v.y);
    float l = m + __logf(__expf(v.x - m) + __expf(v.y - m));
    ((float2*)out_n)[i] = make_float2(v.x - l, v.y - l);
}

extern "C" void kernel_launch(void* const* d_in, const int* in_sizes, int n_in,
                              void* d_out, int out_size) {
    // Identify inputs by element count (robust to ordering & dtype):
    const float *x = 0, *ea = 0, *W1 = 0, *b1 = 0, *We = 0, *be = 0, *W2 = 0, *b2 = 0;
    const int* ei32 = 0;
    for (int i = 0; i < n_in; i++) {
        switch (in_sizes[i]) {
            case 200000:   x    = (const float*)d_in[i]; break;
            case 6400000:  ei32 = (const int*)d_in[i];   break;
            case 12800000: ei32 = (const int*)d_in[i];   break;
            case 3200000:  ea   = (const float*)d_in[i]; break;
            case 132:      We   = (const float*)d_in[i]; break;
            case 16:       b1   = (const float*)d_in[i]; break;
            case 4:        be   = (const float*)d_in[i]; break;
            case 2:        b2   = (const float*)d_in[i]; break;
            case 32:
                if (!W1) W1 = (const float*)d_in[i];
                else     W2 = (const float*)d_in[i];
                break;
            default: break;
        }
    }

    float* out = (float*)d_out;
    float* out_n = out;             // [N,2]
    float* out_e = out + 2 * NN;    // [E,4]

    const int BT = 256;
    const int NB_N = (NN + BT - 1) / BT;
    const int NB_E = (NE + BT - 1) / BT;

    k_detect<<<1, 1>>>(ei32);
    k_init  <<<NB_N, BT>>>();
    k_deg   <<<NB_E, BT>>>(ei32);
    k_nodeA <<<NB_N, BT>>>(x);
    k_scat1 <<<NB_E, BT>>>();
    k_nodeB <<<NB_N, BT>>>(W1, b1, W2, We);
    k_edge  <<<NB_E, BT>>>(ea, We, be, out_e);
    k_nodeC <<<NB_N, BT>>>(b2, out_n);
}